// round 7
// baseline (speedup 1.0000x reference)
#include <cuda_runtime.h>
#include <cuda_fp16.h>
#include <cstdint>
#include <cstddef>

#define NROWS 65536
#define PLANE ((size_t)NROWS * 256)

__device__ __align__(128) __half g_xh [6 * PLANE];
__device__ __align__(128) __half g_q0h[3 * PLANE];
__device__ __align__(128) __half g_qa [3 * PLANE];
__device__ __align__(128) __half g_qb [3 * PLANE];
__device__ __align__(128) __half g_wcat[3 * 256 * 768];

#define SWZ(x) ((x) ^ (((x) >> 3) & 0x70))

// SMEM: bias [0,512), barriers [512,560), 3 stages of (A 16KB + B 16KB) at 1024
#define OFF_BIAS 0
#define OFF_BAR  512
#define OFF_STG  1024
#define SMEM_TOTAL (1024 + 3 * 32768)   // 99328

__device__ __forceinline__ uint32_t s2u(const void* p) {
    return (uint32_t)__cvta_generic_to_shared(p);
}
__device__ __forceinline__ void mbar_init(uint32_t a, uint32_t c) {
    asm volatile("mbarrier.init.shared.b64 [%0], %1;" :: "r"(a), "r"(c) : "memory");
}
__device__ __forceinline__ void mbar_wait(uint32_t a, uint32_t par) {
    uint32_t done;
    asm volatile(
        "{\n\t.reg .pred p;\n\t"
        "mbarrier.try_wait.parity.acquire.cta.shared::cta.b64 p, [%1], %2;\n\t"
        "selp.b32 %0, 1, 0, p;\n\t}"
        : "=r"(done) : "r"(a), "r"(par) : "memory");
    if (!done) {
        asm volatile(
            "{\n\t.reg .pred P1;\n\t"
            "WL_%=:\n\t"
            "mbarrier.try_wait.parity.acquire.cta.shared::cta.b64 P1, [%0], %1, 0x989680;\n\t"
            "@P1 bra.uni WD_%=;\n\t"
            "bra.uni WL_%=;\n\t"
            "WD_%=:\n\t}"
            :: "r"(a), "r"(par) : "memory");
    }
}
#define MBAR_ARRIVE(a) \
    asm volatile("mbarrier.arrive.shared.b64 _, [%0];" :: "r"(a) : "memory")
#define CPA(dst, src) \
    asm volatile("cp.async.cg.shared.global [%0], [%1], 16;" \
                 :: "r"(dst), "l"(src) : "memory")
#define CPA_ARRIVE(bar) \
    asm volatile("cp.async.mbarrier.arrive.noinc.shared.b64 [%0];" \
                 :: "r"(bar) : "memory")
#define LDSM4(r, addr) \
    asm volatile("ldmatrix.sync.aligned.m8n8.x4.shared.b16 {%0,%1,%2,%3}, [%4];" \
                 : "=r"((r)[0]), "=r"((r)[1]), "=r"((r)[2]), "=r"((r)[3]) \
                 : "r"(addr))
#define MMA(cr, av, b0v, b1v) \
    asm volatile("mma.sync.aligned.m16n8k16.row.col.f32.f16.f16.f32 " \
                 "{%0,%1,%2,%3}, {%4,%5,%6,%7}, {%8,%9}, {%0,%1,%2,%3};" \
                 : "+f"((cr)[0]), "+f"((cr)[1]), "+f"((cr)[2]), "+f"((cr)[3]) \
                 : "r"((av)[0]), "r"((av)[1]), "r"((av)[2]), "r"((av)[3]), \
                   "r"(b0v), "r"(b1v))

// ---------------- prep kernels ---------------------------------------------
__global__ void prep_xq_kernel(const float* __restrict__ x,
                               const float* __restrict__ q) {
    size_t idx = (size_t)blockIdx.x * 256 + threadIdx.x;
    const float2* p = reinterpret_cast<const float2*>(x + idx * 6);
    float2 a = p[0], b = p[1], c = p[2];
    g_xh[0 * PLANE + idx] = __float2half(a.x);
    g_xh[1 * PLANE + idx] = __float2half(a.y);
    g_xh[2 * PLANE + idx] = __float2half(b.x);
    g_xh[3 * PLANE + idx] = __float2half(b.y);
    g_xh[4 * PLANE + idx] = __float2half(c.x);
    g_xh[5 * PLANE + idx] = __float2half(c.y);
    g_q0h[0 * PLANE + idx] = __float2half(q[idx * 3 + 0]);
    g_q0h[1 * PLANE + idx] = __float2half(q[idx * 3 + 1]);
    g_q0h[2 * PLANE + idx] = __float2half(q[idx * 3 + 2]);
}
__global__ void prep_w_kernel(const float* __restrict__ W1,
                              const float* __restrict__ W2,
                              const float* __restrict__ W3) {
    uint32_t t = blockIdx.x * 256 + threadIdx.x;   // 3*256*768
    int l = t / 196608, r = t % 196608;
    int o = r / 768, k = r % 768;
    int j = k >> 8, c = k & 255;
    const float* W = (l == 0) ? W1 : (l == 1 ? W2 : W3);
    g_wcat[t] = __float2half(W[(o * 256 + c) * 3 + j]);
}

// ---------------- layer kernel ---------------------------------------------
// grid: (2 n-halves, 512 row-tiles, 3 groups), 256 threads
__global__ void __launch_bounds__(256, 2)
layer_kernel(int qin_sel, int qout_sel, const float* __restrict__ bias, int layer) {
    extern __shared__ char smem[];
    const int tid   = threadIdx.x;
    const int lane  = tid & 31;
    const int wid   = tid >> 5;
    const int warpM = wid & 3;
    const int warpN = wid >> 2;
    const int half  = blockIdx.x;
    const int row0  = blockIdx.y * 128;
    const int g     = blockIdx.z;
    const int ncta  = half * 128;

    const __half* __restrict__ qin =
        (qin_sel == 0) ? g_q0h : (qin_sel == 1 ? g_qa : g_qb);
    __half* __restrict__ qout = (qout_sel == 1) ? g_qa : g_qb;
    const __half* __restrict__ wc = g_wcat + (size_t)layer * (256 * 768);

    const __half* aplane[3];
    aplane[0] = g_xh + (size_t)(2 * g + 0) * PLANE + (size_t)row0 * 256;
    aplane[1] = g_xh + (size_t)(2 * g + 1) * PLANE + (size_t)row0 * 256;
    aplane[2] = qin  + (size_t)g * PLANE          + (size_t)row0 * 256;
    const __half* bsrc = wc + (size_t)ncta * 768;

    float* bias_s = reinterpret_cast<float*>(smem + OFF_BIAS);
    if (tid < 128) bias_s[tid] = bias[ncta + tid];

    const uint32_t sb = s2u(smem);
    const uint32_t FULLB  = sb + OFF_BAR;        // full[s]  at +8s
    const uint32_t EMPTYB = sb + OFF_BAR + 24;   // empty[s] at +8s

    if (tid == 0) {
        #pragma unroll
        for (int s = 0; s < 3; ++s) {
            mbar_init(FULLB  + 8 * s, 256);
            mbar_init(EMPTYB + 8 * s, 256);
        }
    }
    __syncthreads();

    const int ldm = tid >> 3, ldt = (tid & 7) * 8;

    auto produce = [&](int c, int stg) {
        const __half* sA = aplane[c >> 2] + (c & 3) * 64;
        const uint32_t dA = sb + OFF_STG + stg * 32768;
        #pragma unroll
        for (int it = 0; it < 4; ++it) {
            int m = ldm + it * 32;
            CPA(dA + SWZ(m * 128 + ldt * 2), sA + (size_t)m * 256 + ldt);
        }
        const __half* sB = bsrc + c * 64;
        const uint32_t dB = dA + 16384;
        #pragma unroll
        for (int it = 0; it < 4; ++it) {
            int n = ldm + it * 32;
            CPA(dB + SWZ(n * 128 + ldt * 2), sB + (size_t)n * 768 + ldt);
        }
        CPA_ARRIVE(FULLB + 8 * stg);
    };

    float c[2][8][4];
    #pragma unroll
    for (int mt = 0; mt < 2; ++mt)
        #pragma unroll
        for (int j = 0; j < 8; ++j)
            #pragma unroll
            for (int e = 0; e < 4; ++e) c[mt][j][e] = 0.0f;

    const int arow = warpM * 32 + (lane & 15);
    const int akb  = (lane >> 4) * 8;
    const int brow = warpN * 64 + ((lane >> 3) & 2) * 4 + (lane & 7);
    const int bkb  = ((lane >> 3) & 1) * 8;

    uint32_t a[2][2][4], b[2][4][4];

    auto prefetch = [&](int slot, int stg, int k0) {
        const uint32_t aoff = sb + OFF_STG + stg * 32768;
        const uint32_t boff = aoff + 16384;
        #pragma unroll
        for (int mt = 0; mt < 2; ++mt)
            LDSM4(a[slot][mt], aoff + SWZ((arow + mt * 16) * 128 + (k0 + akb) * 2));
        #pragma unroll
        for (int j = 0; j < 4; ++j)
            LDSM4(b[slot][j], boff + SWZ((brow + j * 16) * 128 + (k0 + bkb) * 2));
    };
    auto mmas = [&](int slot) {
        #pragma unroll
        for (int mt = 0; mt < 2; ++mt)
            #pragma unroll
            for (int j = 0; j < 4; ++j) {
                MMA(c[mt][2 * j],     a[slot][mt], b[slot][j][0], b[slot][j][1]);
                MMA(c[mt][2 * j + 1], a[slot][mt], b[slot][j][2], b[slot][j][3]);
            }
    };

    produce(0, 0);
    produce(1, 1);

    mbar_wait(FULLB + 0, 0);
    prefetch(0, 0, 0);

    #pragma unroll 1
    for (int t = 0; t < 4; ++t) {
        #pragma unroll
        for (int s = 0; s < 3; ++s) {
            // iteration i = 3t+s, chunk i in stage s, ks0 frags in slot 0
            prefetch(1, s, 16);
            mmas(0);                                   // ks0

            // produce chunk i+2
            if (s == 0) {
                if (t >= 1) mbar_wait(EMPTYB + 16, (t - 1) & 1);
                produce(3 * t + 2, 2);
            } else if (s == 1) {
                if (t < 3) { mbar_wait(EMPTYB + 0, t & 1); produce(3 * t + 3, 0); }
            } else {
                if (t < 3) { mbar_wait(EMPTYB + 8, t & 1); produce(3 * t + 4, 1); }
            }

            prefetch(0, s, 32);
            mmas(1);                                   // ks1
            prefetch(1, s, 48);
            mmas(0);                                   // ks2

            const bool last = (t == 3) && (s == 2);
            if (!last) {
                const int ns = (s == 2) ? 0 : s + 1;
                const int np = (s == 2) ? ((t + 1) & 1) : (t & 1);
                mbar_wait(FULLB + 8 * ns, np);
                prefetch(0, ns, 0);                    // next chunk ks0
            }
            mmas(1);                                   // ks3
            MBAR_ARRIVE(EMPTYB + 8 * s);
        }
    }

    // epilogue: bias + relu -> fp16 planar (final layer relu lives in finalize)
    __half* plane = qout + (size_t)g * PLANE;
    const int do_relu = (layer != 2);
    #pragma unroll
    for (int mt = 0; mt < 2; ++mt) {
        const int r0 = row0 + warpM * 32 + mt * 16 + (lane >> 2);
        #pragma unroll
        for (int j = 0; j < 8; ++j) {
            const int cl = warpN * 64 + j * 8 + (lane & 3) * 2;
            const float b0 = bias_s[cl], b1 = bias_s[cl + 1];
            float v0 = c[mt][j][0] + b0, v1 = c[mt][j][1] + b1;
            float v2 = c[mt][j][2] + b0, v3 = c[mt][j][3] + b1;
            if (do_relu) {
                v0 = fmaxf(v0, 0.0f); v1 = fmaxf(v1, 0.0f);
                v2 = fmaxf(v2, 0.0f); v3 = fmaxf(v3, 0.0f);
            }
            const int gc = ncta + cl;
            *reinterpret_cast<__half2*>(plane + (size_t)r0 * 256 + gc) =
                __floats2half2_rn(v0, v1);
            *reinterpret_cast<__half2*>(plane + (size_t)(r0 + 8) * 256 + gc) =
                __floats2half2_rn(v2, v3);
        }
    }
}

// ---------------- finalize: residual + relu + interleave -------------------
__global__ void finalize_kernel(const float* __restrict__ q, float* __restrict__ out) {
    size_t idx = (size_t)blockIdx.x * 256 + threadIdx.x;
    #pragma unroll
    for (int g = 0; g < 3; ++g) {
        float v = __half2float(g_qa[(size_t)g * PLANE + idx]) + q[idx * 3 + g];
        out[idx * 3 + g] = fmaxf(v, 0.0f);
    }
}

// ---------------- launch ---------------------------------------------------
extern "C" void kernel_launch(void* const* d_in, const int* in_sizes, int n_in,
                              void* d_out, int out_size) {
    const float* x  = (const float*)d_in[0];
    const float* q  = (const float*)d_in[1];
    const float* W1 = (const float*)d_in[2];
    const float* b1 = (const float*)d_in[3];
    const float* W2 = (const float*)d_in[4];
    const float* b2 = (const float*)d_in[5];
    const float* W3 = (const float*)d_in[6];
    const float* b3 = (const float*)d_in[7];
    float* out = (float*)d_out;

    cudaFuncSetAttribute(layer_kernel,
                         cudaFuncAttributeMaxDynamicSharedMemorySize, SMEM_TOTAL);

    prep_xq_kernel<<<NROWS, 256>>>(x, q);
    prep_w_kernel<<<2304, 256>>>(W1, W2, W3);

    dim3 grid(2, 512, 3);
    layer_kernel<<<grid, 256, SMEM_TOTAL>>>(0, 1, b1, 0);  // q0h -> qa, relu
    layer_kernel<<<grid, 256, SMEM_TOTAL>>>(1, 2, b2, 1);  // qa  -> qb, relu
    layer_kernel<<<grid, 256, SMEM_TOTAL>>>(2, 1, b3, 2);  // qb  -> qa, no relu

    finalize_kernel<<<NROWS, 256>>>(q, out);
}

// round 8
// speedup vs baseline: 1.0464x; 1.0464x over previous
#include <cuda_runtime.h>
#include <cuda_fp16.h>
#include <cstdint>
#include <cstddef>

#define NROWS 65536
#define PLANE ((size_t)NROWS * 256)

__device__ __align__(128) __half g_xh [6 * PLANE];
__device__ __align__(128) __half g_q0h[3 * PLANE];
__device__ __align__(128) __half g_qa [3 * PLANE];
__device__ __align__(128) __half g_qb [3 * PLANE];
__device__ __align__(128) __half g_wcat[3 * 256 * 768];

#define SWZ(x) ((x) ^ (((x) >> 3) & 0x70))

// SMEM: bias 1KB, 4 stages of (A 16KB + B 32KB)
#define OFF_BIAS 0
#define OFF_STG  1024
#define STG_SZ   49152
#define SMEM_TOTAL (1024 + 4 * STG_SZ)   // 197632

__device__ __forceinline__ uint32_t s2u(const void* p) {
    return (uint32_t)__cvta_generic_to_shared(p);
}

#define CPA(dst, src) \
    asm volatile("cp.async.cg.shared.global [%0], [%1], 16;" \
                 :: "r"(dst), "l"(src) : "memory")
#define CPC() asm volatile("cp.async.commit_group;" ::: "memory")
#define CPW2() asm volatile("cp.async.wait_group 2;" ::: "memory")

#define LDSM4(r, addr) \
    asm volatile("ldmatrix.sync.aligned.m8n8.x4.shared.b16 {%0,%1,%2,%3}, [%4];" \
                 : "=r"((r)[0]), "=r"((r)[1]), "=r"((r)[2]), "=r"((r)[3]) \
                 : "r"(addr))

#define MMA(cr, av, b0v, b1v) \
    asm volatile("mma.sync.aligned.m16n8k16.row.col.f32.f16.f16.f32 " \
                 "{%0,%1,%2,%3}, {%4,%5,%6,%7}, {%8,%9}, {%0,%1,%2,%3};" \
                 : "+f"((cr)[0]), "+f"((cr)[1]), "+f"((cr)[2]), "+f"((cr)[3]) \
                 : "r"((av)[0]), "r"((av)[1]), "r"((av)[2]), "r"((av)[3]), \
                   "r"(b0v), "r"(b1v))

// ---------------- prep kernels ---------------------------------------------
__global__ void prep_xq_kernel(const float* __restrict__ x,
                               const float* __restrict__ q) {
    size_t idx = (size_t)blockIdx.x * 256 + threadIdx.x;
    const float2* p = reinterpret_cast<const float2*>(x + idx * 6);
    float2 a = p[0], b = p[1], c = p[2];
    g_xh[0 * PLANE + idx] = __float2half(a.x);
    g_xh[1 * PLANE + idx] = __float2half(a.y);
    g_xh[2 * PLANE + idx] = __float2half(b.x);
    g_xh[3 * PLANE + idx] = __float2half(b.y);
    g_xh[4 * PLANE + idx] = __float2half(c.x);
    g_xh[5 * PLANE + idx] = __float2half(c.y);
    g_q0h[0 * PLANE + idx] = __float2half(q[idx * 3 + 0]);
    g_q0h[1 * PLANE + idx] = __float2half(q[idx * 3 + 1]);
    g_q0h[2 * PLANE + idx] = __float2half(q[idx * 3 + 2]);
}
__global__ void prep_w_kernel(const float* __restrict__ W1,
                              const float* __restrict__ W2,
                              const float* __restrict__ W3) {
    uint32_t t = blockIdx.x * 256 + threadIdx.x;   // 3*256*768
    int l = t / 196608, r = t % 196608;
    int o = r / 768, k = r % 768;
    int j = k >> 8, c = k & 255;
    const float* W = (l == 0) ? W1 : (l == 1 ? W2 : W3);
    g_wcat[t] = __float2half(W[(o * 256 + c) * 3 + j]);
}

// ---------------- layer kernel ---------------------------------------------
// grid: (512 row-tiles, 3 groups), 512 threads; CTA tile 128(M) x 256(N)
__global__ void __launch_bounds__(512, 1)
layer_kernel(int qin_sel, int qout_sel, const float* __restrict__ bias, int layer) {
    extern __shared__ char smem[];
    const int tid   = threadIdx.x;
    const int lane  = tid & 31;
    const int wid   = tid >> 5;
    const int warpM = wid & 3;       // 4 warps in M (32 rows each)
    const int warpN = wid >> 2;      // 4 warps in N (64 cols each)
    const int row0  = blockIdx.x * 128;
    const int g     = blockIdx.y;

    const __half* __restrict__ qin =
        (qin_sel == 0) ? g_q0h : (qin_sel == 1 ? g_qa : g_qb);
    __half* __restrict__ qout = (qout_sel == 1) ? g_qa : g_qb;
    const __half* __restrict__ wc = g_wcat + (size_t)layer * (256 * 768);

    const __half* aplane[3];
    aplane[0] = g_xh + (size_t)(2 * g + 0) * PLANE + (size_t)row0 * 256;
    aplane[1] = g_xh + (size_t)(2 * g + 1) * PLANE + (size_t)row0 * 256;
    aplane[2] = qin  + (size_t)g * PLANE          + (size_t)row0 * 256;

    float* bias_s = reinterpret_cast<float*>(smem + OFF_BIAS);
    if (tid < 256) bias_s[tid] = bias[tid];

    const uint32_t sb = s2u(smem);
    const int ldm = tid >> 3, ldt = (tid & 7) * 8;   // 0..63 rows, col-halfwords

    auto produce = [&](int c, int stg) {
        const __half* sA = aplane[c >> 2] + (c & 3) * 64;
        const uint32_t dA = sb + OFF_STG + stg * STG_SZ;
        #pragma unroll
        for (int it = 0; it < 2; ++it) {           // A: 128 rows x 128B
            int m = ldm + it * 64;
            CPA(dA + SWZ(m * 128 + ldt * 2), sA + (size_t)m * 256 + ldt);
        }
        const __half* sB = wc + c * 64;
        const uint32_t dB = dA + 16384;
        #pragma unroll
        for (int it = 0; it < 4; ++it) {           // B: 256 n-rows x 128B
            int n = ldm + it * 64;
            CPA(dB + SWZ(n * 128 + ldt * 2), sB + (size_t)n * 768 + ldt);
        }
        CPC();
    };

    float c[2][8][4];
    #pragma unroll
    for (int mt = 0; mt < 2; ++mt)
        #pragma unroll
        for (int j = 0; j < 8; ++j)
            #pragma unroll
            for (int e = 0; e < 4; ++e) c[mt][j][e] = 0.0f;

    const int arow = warpM * 32 + (lane & 15);
    const int akb  = (lane >> 4) * 8;
    const int brow = warpN * 64 + ((lane >> 3) & 2) * 4 + (lane & 7);
    const int bkb  = ((lane >> 3) & 1) * 8;

    uint32_t a[2][2][4], b[2][4][4];

    produce(0, 0);
    produce(1, 1);
    produce(2, 2);

    #pragma unroll 1
    for (int i = 0; i < 12; ++i) {
        const int stg = i & 3;
        CPW2();                 // chunks <= i resident (pending: i+1, i+2)
        __syncthreads();        // all warps done reading stage (i+3)&3
        if (i + 3 < 12) produce(i + 3, (i + 3) & 3);
        else CPC();             // keep group accounting uniform

        const uint32_t aoff = sb + OFF_STG + stg * STG_SZ;
        const uint32_t boff = aoff + 16384;

        // prime ks=0 frags
        #pragma unroll
        for (int mt = 0; mt < 2; ++mt)
            LDSM4(a[0][mt], aoff + SWZ((arow + mt * 16) * 128 + akb * 2));
        #pragma unroll
        for (int j = 0; j < 4; ++j)
            LDSM4(b[0][j], boff + SWZ((brow + j * 16) * 128 + bkb * 2));

        #pragma unroll
        for (int ks = 0; ks < 4; ++ks) {
            const int cur = ks & 1, nxt = cur ^ 1;
            if (ks < 3) {
                const int k0 = (ks + 1) * 16;
                #pragma unroll
                for (int mt = 0; mt < 2; ++mt)
                    LDSM4(a[nxt][mt], aoff + SWZ((arow + mt * 16) * 128 + (k0 + akb) * 2));
                #pragma unroll
                for (int j = 0; j < 4; ++j)
                    LDSM4(b[nxt][j], boff + SWZ((brow + j * 16) * 128 + (k0 + bkb) * 2));
            }
            #pragma unroll
            for (int mt = 0; mt < 2; ++mt)
                #pragma unroll
                for (int j = 0; j < 4; ++j) {
                    MMA(c[mt][2 * j],     a[cur][mt], b[cur][j][0], b[cur][j][1]);
                    MMA(c[mt][2 * j + 1], a[cur][mt], b[cur][j][2], b[cur][j][3]);
                }
        }
    }

    // epilogue: bias + relu -> fp16 planar (final layer relu lives in finalize)
    __half* plane = qout + (size_t)g * PLANE;
    const int do_relu = (layer != 2);
    #pragma unroll
    for (int mt = 0; mt < 2; ++mt) {
        const int r0 = row0 + warpM * 32 + mt * 16 + (lane >> 2);
        #pragma unroll
        for (int j = 0; j < 8; ++j) {
            const int cl = warpN * 64 + j * 8 + (lane & 3) * 2;
            const float b0 = bias_s[cl], b1 = bias_s[cl + 1];
            float v0 = c[mt][j][0] + b0, v1 = c[mt][j][1] + b1;
            float v2 = c[mt][j][2] + b0, v3 = c[mt][j][3] + b1;
            if (do_relu) {
                v0 = fmaxf(v0, 0.0f); v1 = fmaxf(v1, 0.0f);
                v2 = fmaxf(v2, 0.0f); v3 = fmaxf(v3, 0.0f);
            }
            *reinterpret_cast<__half2*>(plane + (size_t)r0 * 256 + cl) =
                __floats2half2_rn(v0, v1);
            *reinterpret_cast<__half2*>(plane + (size_t)(r0 + 8) * 256 + cl) =
                __floats2half2_rn(v2, v3);
        }
    }
}

// ---------------- finalize: residual + relu + interleave -------------------
__global__ void finalize_kernel(const float* __restrict__ q, float* __restrict__ out) {
    size_t idx = (size_t)blockIdx.x * 256 + threadIdx.x;
    #pragma unroll
    for (int g = 0; g < 3; ++g) {
        float v = __half2float(g_qa[(size_t)g * PLANE + idx]) + q[idx * 3 + g];
        out[idx * 3 + g] = fmaxf(v, 0.0f);
    }
}

// ---------------- launch ---------------------------------------------------
extern "C" void kernel_launch(void* const* d_in, const int* in_sizes, int n_in,
                              void* d_out, int out_size) {
    const float* x  = (const float*)d_in[0];
    const float* q  = (const float*)d_in[1];
    const float* W1 = (const float*)d_in[2];
    const float* b1 = (const float*)d_in[3];
    const float* W2 = (const float*)d_in[4];
    const float* b2 = (const float*)d_in[5];
    const float* W3 = (const float*)d_in[6];
    const float* b3 = (const float*)d_in[7];
    float* out = (float*)d_out;

    cudaFuncSetAttribute(layer_kernel,
                         cudaFuncAttributeMaxDynamicSharedMemorySize, SMEM_TOTAL);

    prep_xq_kernel<<<NROWS, 256>>>(x, q);
    prep_w_kernel<<<2304, 256>>>(W1, W2, W3);

    dim3 grid(512, 3);
    layer_kernel<<<grid, 512, SMEM_TOTAL>>>(0, 1, b1, 0);  // q0h -> qa, relu
    layer_kernel<<<grid, 512, SMEM_TOTAL>>>(1, 2, b2, 1);  // qa  -> qb, relu
    layer_kernel<<<grid, 512, SMEM_TOTAL>>>(2, 1, b3, 2);  // qb  -> qa, no relu

    finalize_kernel<<<NROWS, 256>>>(q, out);
}